// round 2
// baseline (speedup 1.0000x reference)
#include <cuda_runtime.h>
#include <math.h>

// Problem constants
constexpr int B = 64;
constexpr int T = 512;
constexpr int E = 256;
constexpr int H = 512;
constexpr int K = 24;
constexpr int G = 4 * H;          // 2048
constexpr int H2 = 2 * H;         // 1024
constexpr int START_TAG = 22;
constexpr int STOP_TAG = 23;
constexpr float NEG = -10000.0f;
constexpr int M_ROWS = B * T;     // 32768

constexpr int NBLK = 128;         // persistent recurrence blocks (<=148 SMs)
constexpr int WSP = 516;          // padded smem row stride for weights

// ------------------------- device scratch (static, no allocs) ----------------
__device__ float g_x[B * T * E];
__device__ float g_xg[2][B * T * G];        // input-gate precompute per dir
__device__ float g_h0[B * T * H2];
__device__ float g_h1[B * T * H2];
__device__ float g_hbuf[2][2][H * B];       // [dir][parity][k*64+b]  k-major h state
__device__ float g_feats[B * T * K];
__device__ unsigned g_barcnt;
__device__ unsigned g_bargen;

// ------------------------- embedding lookup ---------------------------------
__global__ void embed_kernel(const int* __restrict__ sentence,
                             const float* __restrict__ embed) {
    int i = blockIdx.x * blockDim.x + threadIdx.x;
    if (i >= B * T * E) return;
    int e = i % E;
    int bt = i / E;
    g_x[i] = embed[(long long)sentence[bt] * E + e];
}

// ------------------------- batched GEMM: C = A * W^T + bias -----------------
__global__ __launch_bounds__(256)
void gemm_bias_kernel(int a_sel, const float* __restrict__ W,
                      const float* __restrict__ bias, int c_dir, int Kd) {
    const float* __restrict__ A = a_sel ? g_h0 : g_x;
    float* __restrict__ C = g_xg[c_dir];

    __shared__ float As[16][68];
    __shared__ float Ws[16][68];

    int n0 = blockIdx.x * 64;
    int m0 = blockIdx.y * 64;
    int tid = threadIdx.x;
    int tx = tid & 15;
    int ty = tid >> 4;
    int tm0 = ty * 4;
    int tn0 = tx * 4;

    float acc[4][4] = {};

    for (int k0 = 0; k0 < Kd; k0 += 16) {
        #pragma unroll
        for (int i = 0; i < 4; i++) {
            int e = tid + i * 256;
            int k = e & 15;
            int m = e >> 4;
            As[k][m] = A[(m0 + m) * Kd + k0 + k];
            Ws[k][m] = W[(n0 + m) * Kd + k0 + k];
        }
        __syncthreads();
        #pragma unroll
        for (int k = 0; k < 16; k++) {
            float4 a = *(const float4*)&As[k][tm0];
            float4 w = *(const float4*)&Ws[k][tn0];
            float av[4] = {a.x, a.y, a.z, a.w};
            float wv[4] = {w.x, w.y, w.z, w.w};
            #pragma unroll
            for (int i = 0; i < 4; i++)
                #pragma unroll
                for (int j = 0; j < 4; j++)
                    acc[i][j] += av[i] * wv[j];
        }
        __syncthreads();
    }

    #pragma unroll
    for (int i = 0; i < 4; i++)
        #pragma unroll
        for (int j = 0; j < 4; j++)
            C[(m0 + tm0 + i) * G + n0 + tn0 + j] = acc[i][j] + bias[n0 + tn0 + j];
}

// ------------------------- grid barrier --------------------------------------
__device__ __forceinline__ void grid_barrier() {
    __syncthreads();
    if (threadIdx.x == 0) {
        __threadfence();                               // release my writes
        volatile unsigned* gv = &g_bargen;
        unsigned gen = *gv;
        unsigned ticket = atomicAdd(&g_barcnt, 1);     // never reset; mod NBLK
        if ((ticket + 1u) % (unsigned)NBLK == 0u) {
            atomicAdd(&g_bargen, 1u);
        } else {
            while (*gv == gen) { }
        }
        __threadfence();                               // acquire
    }
    __syncthreads();
}

// ------------------------- persistent bidirectional LSTM layer ---------------
// Block bx: dir = bx>>6, h-slice h0 = (bx&63)*8. Owns 32 gate rows
// (4 gates x 8 h). Weights cached in SMEM for all T steps. One grid barrier
// per step; h state ping-pongs in k-major global buffers.
__global__ __launch_bounds__(256, 1)
void lstm_layer_kernel(const float* __restrict__ whh_f,
                       const float* __restrict__ whh_b, int layer) {
    extern __shared__ float sm[];
    float* ws  = sm;                       // [32][WSP]
    float* hs  = ws + 32 * WSP;            // [32][68]
    float* gsm = hs + 32 * 68;             // [32][65]
    float* csm = gsm + 32 * 65;            // [8][64]

    int tid = threadIdx.x;
    int bx = blockIdx.x;
    int dir = bx >> 6;
    int h0 = (bx & 63) * 8;
    const float* __restrict__ Wm = dir ? whh_b : whh_f;
    const float* __restrict__ xg = g_xg[dir];
    float* __restrict__ hout = layer ? g_h1 : g_h0;

    int tx = tid & 15;          // batch group: b0 = tx*4
    int ty = tid >> 4;          // row group:   r0 = ty*2
    int b0 = tx * 4;
    int r0 = ty * 2;

    // ---- load this block's 32 weight rows into SMEM (once) ----
    #pragma unroll
    for (int i = 0; i < 16; i++) {
        int v = tid + i * 256;             // 0..4095 float4s
        int r = v >> 7;                    // 0..31
        int k4 = v & 127;                  // 0..127
        int n = (r >> 3) * H + h0 + (r & 7);
        float4 w = *(const float4*)&Wm[n * H + k4 * 4];
        *(float4*)&ws[r * WSP + k4 * 4] = w;
    }

    // ---- zero c (smem) and h parity-0 buffer (global slice) ----
    for (int i = tid; i < 8 * 64; i += 256) csm[i] = 0.0f;
    {
        float* z = g_hbuf[dir][0];
        // this block zeros k-rows h0..h0+7 -> 8*64 floats
        for (int i = tid; i < 8 * 64; i += 256) z[h0 * 64 + i] = 0.0f;
    }
    grid_barrier();

    for (int s = 0; s < T; s++) {
        int p = s & 1;
        int t = dir ? (T - 1 - s) : s;
        const float* __restrict__ hcur = g_hbuf[dir][p];
        float* __restrict__ hnext = g_hbuf[dir][p ^ 1];

        float acc[2][4] = {};

        for (int k0 = 0; k0 < H; k0 += 32) {
            // stage h chunk [32 k][64 b] into smem (L2-coherent loads)
            #pragma unroll
            for (int i = 0; i < 2; i++) {
                int v = tid + i * 256;     // 0..511 float4s
                int k = v >> 4;
                int b4 = (v & 15) * 4;
                float4 hv = __ldcg((const float4*)&hcur[(k0 + k) * 64 + b4]);
                *(float4*)&hs[k * 68 + b4] = hv;
            }
            __syncthreads();
            #pragma unroll
            for (int k = 0; k < 32; k++) {
                float w0 = ws[(r0 + 0) * WSP + k0 + k];
                float w1 = ws[(r0 + 1) * WSP + k0 + k];
                float4 hv = *(const float4*)&hs[k * 68 + b0];
                float hvv[4] = {hv.x, hv.y, hv.z, hv.w};
                #pragma unroll
                for (int j = 0; j < 4; j++) {
                    acc[0][j] += w0 * hvv[j];
                    acc[1][j] += w1 * hvv[j];
                }
            }
            __syncthreads();
        }

        // add xg and stash gates in smem
        #pragma unroll
        for (int i = 0; i < 2; i++) {
            int r = r0 + i;
            int n = (r >> 3) * H + h0 + (r & 7);
            #pragma unroll
            for (int j = 0; j < 4; j++) {
                int b = b0 + j;
                float x = __ldg(&xg[((size_t)b * T + t) * G + n]);
                gsm[r * 65 + b] = acc[i][j] + x;
            }
        }
        __syncthreads();

        // pointwise LSTM update for this block's 8 h x 64 b
        #pragma unroll
        for (int rep = 0; rep < 2; rep++) {
            int e = tid + rep * 256;       // 0..511
            int hi = e >> 6;
            int b = e & 63;
            float gi = gsm[(0 * 8 + hi) * 65 + b];
            float gf = gsm[(1 * 8 + hi) * 65 + b];
            float gc = gsm[(2 * 8 + hi) * 65 + b];
            float go = gsm[(3 * 8 + hi) * 65 + b];

            float si = 1.0f / (1.0f + expf(-gi));
            float sf = 1.0f / (1.0f + expf(-gf));
            float so = 1.0f / (1.0f + expf(-go));

            float c = csm[hi * 64 + b];
            c = sf * c + si * tanhf(gc);
            float hn = so * tanhf(c);
            csm[hi * 64 + b] = c;

            hnext[(h0 + hi) * 64 + b] = hn;
            hout[((size_t)b * T + t) * H2 + dir * H + h0 + hi] = hn;
        }

        grid_barrier();   // includes __syncthreads + fences
    }
}

// ------------------------- output projection (K=24) --------------------------
__global__ __launch_bounds__(256)
void proj_kernel(const float* __restrict__ w_out, const float* __restrict__ b_out) {
    int bt = blockIdx.x;
    int wid = threadIdx.x >> 5;
    int lane = threadIdx.x & 31;
    const float* hrow = g_h1 + (long long)bt * H2;

    for (int j = wid; j < K; j += 8) {
        const float* wr = w_out + j * H2;
        float s = 0.0f;
        for (int k = lane; k < H2; k += 32)
            s += hrow[k] * wr[k];
        #pragma unroll
        for (int off = 16; off; off >>= 1)
            s += __shfl_xor_sync(0xffffffff, s, off);
        if (lane == 0)
            g_feats[bt * K + j] = s + b_out[j];
    }
}

// ------------------------- Viterbi decode ------------------------------------
__global__ void viterbi_kernel(const float* __restrict__ trans,
                               float* __restrict__ out, int out_size) {
    int b = blockIdx.x;
    int tid = threadIdx.x;

    __shared__ float tr[K][K];
    __shared__ float v[K];
    __shared__ float vn[K];
    __shared__ unsigned char bp[T][K];

    for (int i = tid; i < K * K; i += 32)
        tr[i / K][i % K] = trans[i];
    if (tid < K)
        v[tid] = (tid == START_TAG) ? 0.0f : NEG;
    __syncthreads();

    for (int t = 0; t < T; t++) {
        if (tid < K) {
            float best = -3.4e38f;
            int arg = 0;
            #pragma unroll
            for (int kp = 0; kp < K; kp++) {
                float sc = v[kp] + tr[tid][kp];
                if (sc > best) { best = sc; arg = kp; }
            }
            vn[tid] = best + g_feats[(b * T + t) * K + tid];
            bp[t][tid] = (unsigned char)arg;
        }
        __syncthreads();
        if (tid < K) v[tid] = vn[tid];
        __syncthreads();
    }

    if (tid == 0) {
        float best = -3.4e38f;
        int arg = 0;
        for (int k = 0; k < K; k++) {
            float sc = v[k] + tr[STOP_TAG][k];
            if (sc > best) { best = sc; arg = k; }
        }
        if (out_size >= B + B * T) {
            out[b] = best;
            int tag = arg;
            for (int t = T - 1; t >= 0; t--) {
                out[B + b * T + t] = (float)tag;
                tag = bp[t][tag];
            }
        } else if (out_size >= B * T) {
            int tag = arg;
            for (int t = T - 1; t >= 0; t--) {
                out[b * T + t] = (float)tag;
                tag = bp[t][tag];
            }
        } else {
            out[b] = best;
        }
    }
}

// ------------------------- launch --------------------------------------------
extern "C" void kernel_launch(void* const* d_in, const int* in_sizes, int n_in,
                              void* d_out, int out_size) {
    const int*   sentence = (const int*)d_in[0];
    const float* embed    = (const float*)d_in[1];
    const float* w_ih_l0f = (const float*)d_in[2];
    const float* w_hh_l0f = (const float*)d_in[3];
    const float* b_l0f    = (const float*)d_in[4];
    const float* w_ih_l0b = (const float*)d_in[5];
    const float* w_hh_l0b = (const float*)d_in[6];
    const float* b_l0b    = (const float*)d_in[7];
    const float* w_ih_l1f = (const float*)d_in[8];
    const float* w_hh_l1f = (const float*)d_in[9];
    const float* b_l1f    = (const float*)d_in[10];
    const float* w_ih_l1b = (const float*)d_in[11];
    const float* w_hh_l1b = (const float*)d_in[12];
    const float* b_l1b    = (const float*)d_in[13];
    const float* w_out    = (const float*)d_in[14];
    const float* b_out    = (const float*)d_in[15];
    const float* trans    = (const float*)d_in[16];
    float* out = (float*)d_out;

    static bool attr_done = false;
    const int dyn_smem = (32 * WSP + 32 * 68 + 32 * 65 + 8 * 64) * 4;
    if (!attr_done) {
        cudaFuncSetAttribute(lstm_layer_kernel,
                             cudaFuncAttributeMaxDynamicSharedMemorySize, dyn_smem);
        attr_done = true;
    }

    // 1. embedding
    embed_kernel<<<(B * T * E + 255) / 256, 256>>>(sentence, embed);

    // 2. layer-0 input-gate GEMMs (M=32768, N=2048, K=256)
    dim3 ggrid(G / 64, M_ROWS / 64);
    gemm_bias_kernel<<<ggrid, 256>>>(0, w_ih_l0f, b_l0f, 0, E);
    gemm_bias_kernel<<<ggrid, 256>>>(0, w_ih_l0b, b_l0b, 1, E);

    // 3. layer-0 recurrence (persistent, 1 launch)
    lstm_layer_kernel<<<NBLK, 256, dyn_smem>>>(w_hh_l0f, w_hh_l0b, 0);

    // 4. layer-1 input-gate GEMMs (K=1024)
    gemm_bias_kernel<<<ggrid, 256>>>(1, w_ih_l1f, b_l1f, 0, H2);
    gemm_bias_kernel<<<ggrid, 256>>>(1, w_ih_l1b, b_l1b, 1, H2);

    // 5. layer-1 recurrence
    lstm_layer_kernel<<<NBLK, 256, dyn_smem>>>(w_hh_l1f, w_hh_l1b, 1);

    // 6. emission features
    proj_kernel<<<B * T, 256>>>(w_out, b_out);

    // 7. Viterbi decode + output
    viterbi_kernel<<<B, 32>>>(trans, out, out_size);
}

// round 3
// speedup vs baseline: 1.2052x; 1.2052x over previous
#include <cuda_runtime.h>
#include <math.h>

// Problem constants
constexpr int B = 64;
constexpr int T = 512;
constexpr int E = 256;
constexpr int H = 512;
constexpr int K = 24;
constexpr int G = 4 * H;          // 2048
constexpr int H2 = 2 * H;         // 1024
constexpr int START_TAG = 22;
constexpr int STOP_TAG = 23;
constexpr float NEG = -10000.0f;
constexpr int M_ROWS = B * T;     // 32768

constexpr int NBLK = 128;         // persistent recurrence blocks (<=148 SMs)
constexpr int WKP = 36;           // ws row stride (floats)

// ------------------------- device scratch (static, no allocs) ----------------
__device__ float g_x[B * T * E];
__device__ float g_xg[2][T * G * B / 1 ];     // [dir][(t*G+n)*B + b]  (t-major, b-minor)
__device__ float g_h0[B * T * H2];
__device__ float g_h1[B * T * H2];
__device__ float g_hbuf[2][2][H * B];         // [dir][parity][k*64+b]
__device__ float g_feats[B * T * K];
__device__ unsigned g_barcnt;
__device__ unsigned g_bargen;

// ------------------------- small helpers -------------------------------------
static __device__ __forceinline__ unsigned smem_u32(const void* p) {
    unsigned r;
    asm("{ .reg .u64 t; cvta.to.shared.u64 t, %1; cvt.u32.u64 %0, t; }"
        : "=r"(r) : "l"(p));
    return r;
}
static __device__ __forceinline__ void cp_async16(unsigned dst, const void* src) {
    asm volatile("cp.async.cg.shared.global [%0], [%1], 16;\n" :: "r"(dst), "l"(src));
}
static __device__ __forceinline__ void cp_commit() {
    asm volatile("cp.async.commit_group;\n" ::: "memory");
}
template <int N>
static __device__ __forceinline__ void cp_wait() {
    asm volatile("cp.async.wait_group %0;\n" :: "n"(N) : "memory");
}

// ------------------------- embedding lookup ----------------------------------
__global__ void embed_kernel(const int* __restrict__ sentence,
                             const float* __restrict__ embed) {
    int i = blockIdx.x * blockDim.x + threadIdx.x;
    if (i >= B * T * E) return;
    int e = i % E;
    int bt = i / E;
    g_x[i] = embed[(long long)sentence[bt] * E + e];
}

// ------------------------- big GEMM: xg_t = A * W^T + bias -------------------
// A: [M_ROWS, Kd] (g_x or g_h0), W: [G, Kd].
// Output layout: g_xg[dir][(t*G + n)*64 + b]  with m = b*T + t.
// 128x128 tile, BK=16, 256 threads, 8x8 microtile, reg double-buffered loads.
__global__ __launch_bounds__(256)
void gemm_bias_kernel(int a_sel, const float* __restrict__ W,
                      const float* __restrict__ bias, int c_dir, int Kd) {
    const float* __restrict__ A = a_sel ? g_h0 : g_x;
    float* __restrict__ C = g_xg[c_dir];

    __shared__ float As[2][16][132];
    __shared__ float Ws[2][16][132];

    int n0 = blockIdx.x * 128;
    int m0 = blockIdx.y * 128;
    int tid = threadIdx.x;
    int tx = tid & 15;
    int ty = tid >> 4;
    int tm0 = ty * 8;
    int tn0 = tx * 8;

    // global load indices: v = tid*2 + i -> row = v>>2 (0..127), kc = v&3
    int lrow0 = (tid * 2) >> 2;
    int lkc0 = (tid * 2) & 3;
    int lrow1 = (tid * 2 + 1) >> 2;
    int lkc1 = (tid * 2 + 1) & 3;

    float acc[8][8] = {};
    float4 ra0, ra1, rw0, rw1;

    // prologue: load tile 0
    ra0 = *(const float4*)&A[(size_t)(m0 + lrow0) * Kd + lkc0 * 4];
    ra1 = *(const float4*)&A[(size_t)(m0 + lrow1) * Kd + lkc1 * 4];
    rw0 = *(const float4*)&W[(size_t)(n0 + lrow0) * Kd + lkc0 * 4];
    rw1 = *(const float4*)&W[(size_t)(n0 + lrow1) * Kd + lkc1 * 4];
    {
        float* a0 = &As[0][lkc0 * 4][lrow0];
        a0[0 * 132] = ra0.x; a0[1 * 132] = ra0.y; a0[2 * 132] = ra0.z; a0[3 * 132] = ra0.w;
        float* a1 = &As[0][lkc1 * 4][lrow1];
        a1[0 * 132] = ra1.x; a1[1 * 132] = ra1.y; a1[2 * 132] = ra1.z; a1[3 * 132] = ra1.w;
        float* w0 = &Ws[0][lkc0 * 4][lrow0];
        w0[0 * 132] = rw0.x; w0[1 * 132] = rw0.y; w0[2 * 132] = rw0.z; w0[3 * 132] = rw0.w;
        float* w1 = &Ws[0][lkc1 * 4][lrow1];
        w1[0 * 132] = rw1.x; w1[1 * 132] = rw1.y; w1[2 * 132] = rw1.z; w1[3 * 132] = rw1.w;
    }
    __syncthreads();

    int nK = Kd / 16;
    for (int kt = 0; kt < nK; kt++) {
        int buf = kt & 1;
        if (kt + 1 < nK) {
            int k0 = (kt + 1) * 16;
            ra0 = *(const float4*)&A[(size_t)(m0 + lrow0) * Kd + k0 + lkc0 * 4];
            ra1 = *(const float4*)&A[(size_t)(m0 + lrow1) * Kd + k0 + lkc1 * 4];
            rw0 = *(const float4*)&W[(size_t)(n0 + lrow0) * Kd + k0 + lkc0 * 4];
            rw1 = *(const float4*)&W[(size_t)(n0 + lrow1) * Kd + k0 + lkc1 * 4];
        }
        #pragma unroll
        for (int k = 0; k < 16; k++) {
            float4 a0 = *(const float4*)&As[buf][k][tm0];
            float4 a1 = *(const float4*)&As[buf][k][tm0 + 4];
            float4 w0 = *(const float4*)&Ws[buf][k][tn0];
            float4 w1 = *(const float4*)&Ws[buf][k][tn0 + 4];
            float av[8] = {a0.x, a0.y, a0.z, a0.w, a1.x, a1.y, a1.z, a1.w};
            float wv[8] = {w0.x, w0.y, w0.z, w0.w, w1.x, w1.y, w1.z, w1.w};
            #pragma unroll
            for (int i = 0; i < 8; i++)
                #pragma unroll
                for (int j = 0; j < 8; j++)
                    acc[i][j] += av[i] * wv[j];
        }
        if (kt + 1 < nK) {
            int nbuf = buf ^ 1;
            float* a0 = &As[nbuf][lkc0 * 4][lrow0];
            a0[0 * 132] = ra0.x; a0[1 * 132] = ra0.y; a0[2 * 132] = ra0.z; a0[3 * 132] = ra0.w;
            float* a1 = &As[nbuf][lkc1 * 4][lrow1];
            a1[0 * 132] = ra1.x; a1[1 * 132] = ra1.y; a1[2 * 132] = ra1.z; a1[3 * 132] = ra1.w;
            float* w0 = &Ws[nbuf][lkc0 * 4][lrow0];
            w0[0 * 132] = rw0.x; w0[1 * 132] = rw0.y; w0[2 * 132] = rw0.z; w0[3 * 132] = rw0.w;
            float* w1 = &Ws[nbuf][lkc1 * 4][lrow1];
            w1[0 * 132] = rw1.x; w1[1 * 132] = rw1.y; w1[2 * 132] = rw1.z; w1[3 * 132] = rw1.w;
        }
        __syncthreads();
    }

    // epilogue: m = b*T + t ; tile has single b (m0 multiple of 128, T=512)
    int b = m0 >> 9;            // m0 / T
    int t0 = m0 & 511;          // m0 % T
    #pragma unroll
    for (int i = 0; i < 8; i++) {
        int t = t0 + tm0 + i;
        #pragma unroll
        for (int j = 0; j < 8; j++) {
            int n = n0 + tn0 + j;
            C[((size_t)t * G + n) * B + b] = acc[i][j] + bias[n];
        }
    }
}

// ------------------------- grid barrier --------------------------------------
__device__ __forceinline__ void grid_barrier() {
    __syncthreads();
    if (threadIdx.x == 0) {
        __threadfence();
        volatile unsigned* gv = &g_bargen;
        unsigned gen = *gv;
        unsigned ticket = atomicAdd(&g_barcnt, 1);
        if ((ticket + 1u) % (unsigned)NBLK == 0u) {
            atomicAdd(&g_bargen, 1u);
        } else {
            while (*gv == gen) { }
        }
        __threadfence();
    }
    __syncthreads();
}

// ------------------------- persistent bidirectional LSTM layer ---------------
// Block bx: dir = bx>>6, h-slice h0 = (bx&63)*8 (32 gate rows).
// ws[k][r] transposed in SMEM; h state chunks cp.async double-buffered.
__global__ __launch_bounds__(256, 1)
void lstm_layer_kernel(const float* __restrict__ whh_f,
                       const float* __restrict__ whh_b, int layer) {
    extern __shared__ float sm[];
    float* ws  = sm;                        // [512][WKP]
    float* hs  = ws + 512 * WKP;            // [2][128*64]
    float* gsm = hs + 2 * 128 * 64;         // [32][66]
    float* csm = gsm + 32 * 66;             // [8][64]

    int tid = threadIdx.x;
    int bx = blockIdx.x;
    int dir = bx >> 6;
    int h0 = (bx & 63) * 8;
    const float* __restrict__ Wm = dir ? whh_b : whh_f;
    const float* __restrict__ xg = g_xg[dir];
    float* __restrict__ hout = layer ? g_h1 : g_h0;

    int tx = tid & 31;          // b0 = tx*2
    int ty = tid >> 5;          // r0 = ty*4
    int b0 = tx * 2;
    int r0 = ty * 4;

    unsigned hs_u32 = smem_u32(hs);

    // ---- load + transpose weights into SMEM (once) ----
    {
        int r = tid >> 3;                   // 0..31
        int n = (r >> 3) * H + h0 + (r & 7);
        const float* wrow = &Wm[(size_t)n * H];
        #pragma unroll
        for (int it = 0; it < 16; it++) {
            int kc4 = (tid & 7) + it * 8;   // float4 idx 0..127
            float4 w = *(const float4*)&wrow[kc4 * 4];
            float* d = &ws[(kc4 * 4) * WKP + r];
            d[0 * WKP] = w.x; d[1 * WKP] = w.y; d[2 * WKP] = w.z; d[3 * WKP] = w.w;
        }
    }

    // ---- zero c and parity-0 h slice ----
    for (int i = tid; i < 8 * 64; i += 256) csm[i] = 0.0f;
    {
        float* z = g_hbuf[dir][0];
        for (int i = tid; i < 8 * 64; i += 256) z[h0 * 64 + i] = 0.0f;
    }
    grid_barrier();

    for (int s = 0; s < T; s++) {
        int p = s & 1;
        int t = dir ? (T - 1 - s) : s;
        const float* __restrict__ hcur = g_hbuf[dir][p];
        float* __restrict__ hnext = g_hbuf[dir][p ^ 1];

        // prefetch xg for this step (coalesced: [t][n][b] layout)
        float2 xv[4];
        #pragma unroll
        for (int i = 0; i < 4; i++) {
            int r = r0 + i;
            int n = (r >> 3) * H + h0 + (r & 7);
            xv[i] = __ldg((const float2*)&xg[((size_t)t * G + n) * B + b0]);
        }

        float acc[4][2] = {};

        // chunk 0 async load
        #pragma unroll
        for (int j = 0; j < 8; j++) {
            int f4 = tid + j * 256;
            cp_async16(hs_u32 + f4 * 16, &hcur[f4 * 4]);
        }
        cp_commit();

        #pragma unroll
        for (int c = 0; c < 4; c++) {
            int buf = c & 1;
            if (c < 3) {
                int nbuf = buf ^ 1;
                #pragma unroll
                for (int j = 0; j < 8; j++) {
                    int f4 = tid + j * 256;
                    cp_async16(hs_u32 + (nbuf * 8192 + f4 * 4) * 4,
                               &hcur[(c + 1) * 8192 + f4 * 4]);
                }
                cp_commit();
                cp_wait<1>();
            } else {
                cp_wait<0>();
            }
            __syncthreads();

            const float* hb = &hs[buf * 8192];
            const float* wb = &ws[(c * 128) * WKP];
            #pragma unroll 4
            for (int k = 0; k < 128; k++) {
                float4 w = *(const float4*)&wb[k * WKP + r0];
                float2 h = *(const float2*)&hb[k * 64 + b0];
                float wv[4] = {w.x, w.y, w.z, w.w};
                #pragma unroll
                for (int i = 0; i < 4; i++) {
                    acc[i][0] += wv[i] * h.x;
                    acc[i][1] += wv[i] * h.y;
                }
            }
            __syncthreads();
        }

        // gates -> smem
        #pragma unroll
        for (int i = 0; i < 4; i++) {
            int r = r0 + i;
            *(float2*)&gsm[r * 66 + b0] =
                make_float2(acc[i][0] + xv[i].x, acc[i][1] + xv[i].y);
        }
        __syncthreads();

        // pointwise LSTM update (8 h x 64 b per block)
        #pragma unroll
        for (int rep = 0; rep < 2; rep++) {
            int e = tid + rep * 256;
            int hi = e >> 6;
            int b = e & 63;
            float gi = gsm[(0 * 8 + hi) * 66 + b];
            float gf = gsm[(1 * 8 + hi) * 66 + b];
            float gc = gsm[(2 * 8 + hi) * 66 + b];
            float go = gsm[(3 * 8 + hi) * 66 + b];

            float si = 1.0f / (1.0f + expf(-gi));
            float sf = 1.0f / (1.0f + expf(-gf));
            float so = 1.0f / (1.0f + expf(-go));

            float c = csm[hi * 64 + b];
            c = sf * c + si * tanhf(gc);
            float hn = so * tanhf(c);
            csm[hi * 64 + b] = c;

            hnext[(h0 + hi) * 64 + b] = hn;
            hout[((size_t)b * T + t) * H2 + dir * H + h0 + hi] = hn;
        }

        grid_barrier();
    }
}

// ------------------------- output projection (K=24) --------------------------
__global__ __launch_bounds__(256)
void proj_kernel(const float* __restrict__ w_out, const float* __restrict__ b_out) {
    int bt = blockIdx.x;
    int wid = threadIdx.x >> 5;
    int lane = threadIdx.x & 31;
    const float* hrow = g_h1 + (long long)bt * H2;

    for (int j = wid; j < K; j += 8) {
        const float* wr = w_out + j * H2;
        float s = 0.0f;
        for (int k = lane; k < H2; k += 32)
            s += hrow[k] * wr[k];
        #pragma unroll
        for (int off = 16; off; off >>= 1)
            s += __shfl_xor_sync(0xffffffff, s, off);
        if (lane == 0)
            g_feats[bt * K + j] = s + b_out[j];
    }
}

// ------------------------- Viterbi decode ------------------------------------
__global__ void viterbi_kernel(const float* __restrict__ trans,
                               float* __restrict__ out, int out_size) {
    int b = blockIdx.x;
    int tid = threadIdx.x;

    __shared__ float tr[K][K];
    __shared__ float v[K];
    __shared__ float vn[K];
    __shared__ unsigned char bp[T][K];

    for (int i = tid; i < K * K; i += 32)
        tr[i / K][i % K] = trans[i];
    if (tid < K)
        v[tid] = (tid == START_TAG) ? 0.0f : NEG;
    __syncthreads();

    for (int t = 0; t < T; t++) {
        if (tid < K) {
            float best = -3.4e38f;
            int arg = 0;
            #pragma unroll
            for (int kp = 0; kp < K; kp++) {
                float sc = v[kp] + tr[tid][kp];
                if (sc > best) { best = sc; arg = kp; }
            }
            vn[tid] = best + g_feats[(b * T + t) * K + tid];
            bp[t][tid] = (unsigned char)arg;
        }
        __syncthreads();
        if (tid < K) v[tid] = vn[tid];
        __syncthreads();
    }

    if (tid == 0) {
        float best = -3.4e38f;
        int arg = 0;
        for (int k = 0; k < K; k++) {
            float sc = v[k] + tr[STOP_TAG][k];
            if (sc > best) { best = sc; arg = k; }
        }
        if (out_size >= B + B * T) {
            out[b] = best;
            int tag = arg;
            for (int t = T - 1; t >= 0; t--) {
                out[B + b * T + t] = (float)tag;
                tag = bp[t][tag];
            }
        } else if (out_size >= B * T) {
            int tag = arg;
            for (int t = T - 1; t >= 0; t--) {
                out[b * T + t] = (float)tag;
                tag = bp[t][tag];
            }
        } else {
            out[b] = best;
        }
    }
}

// ------------------------- launch --------------------------------------------
extern "C" void kernel_launch(void* const* d_in, const int* in_sizes, int n_in,
                              void* d_out, int out_size) {
    const int*   sentence = (const int*)d_in[0];
    const float* embed    = (const float*)d_in[1];
    const float* w_ih_l0f = (const float*)d_in[2];
    const float* w_hh_l0f = (const float*)d_in[3];
    const float* b_l0f    = (const float*)d_in[4];
    const float* w_ih_l0b = (const float*)d_in[5];
    const float* w_hh_l0b = (const float*)d_in[6];
    const float* b_l0b    = (const float*)d_in[7];
    const float* w_ih_l1f = (const float*)d_in[8];
    const float* w_hh_l1f = (const float*)d_in[9];
    const float* b_l1f    = (const float*)d_in[10];
    const float* w_ih_l1b = (const float*)d_in[11];
    const float* w_hh_l1b = (const float*)d_in[12];
    const float* b_l1b    = (const float*)d_in[13];
    const float* w_out    = (const float*)d_in[14];
    const float* b_out    = (const float*)d_in[15];
    const float* trans    = (const float*)d_in[16];
    float* out = (float*)d_out;

    static bool attr_done = false;
    const int dyn_smem = (512 * WKP + 2 * 128 * 64 + 32 * 66 + 8 * 64) * 4;
    if (!attr_done) {
        cudaFuncSetAttribute(lstm_layer_kernel,
                             cudaFuncAttributeMaxDynamicSharedMemorySize, dyn_smem);
        attr_done = true;
    }

    // 1. embedding
    embed_kernel<<<(B * T * E + 255) / 256, 256>>>(sentence, embed);

    // 2. layer-0 input-gate GEMMs (Kd=256)
    dim3 ggrid(G / 128, M_ROWS / 128);
    gemm_bias_kernel<<<ggrid, 256>>>(0, w_ih_l0f, b_l0f, 0, E);
    gemm_bias_kernel<<<ggrid, 256>>>(0, w_ih_l0b, b_l0b, 1, E);

    // 3. layer-0 recurrence (persistent)
    lstm_layer_kernel<<<NBLK, 256, dyn_smem>>>(w_hh_l0f, w_hh_l0b, 0);

    // 4. layer-1 input-gate GEMMs (Kd=1024)
    gemm_bias_kernel<<<ggrid, 256>>>(1, w_ih_l1f, b_l1f, 0, H2);
    gemm_bias_kernel<<<ggrid, 256>>>(1, w_ih_l1b, b_l1b, 1, H2);

    // 5. layer-1 recurrence
    lstm_layer_kernel<<<NBLK, 256, dyn_smem>>>(w_hh_l1f, w_hh_l1b, 1);

    // 6. emission features
    proj_kernel<<<B * T, 256>>>(w_out, b_out);

    // 7. Viterbi decode + output
    viterbi_kernel<<<B, 32>>>(trans, out, out_size);
}

// round 4
// speedup vs baseline: 1.2576x; 1.0435x over previous
#include <cuda_runtime.h>
#include <math.h>

// Problem constants
constexpr int B = 64;
constexpr int T = 512;
constexpr int E = 256;
constexpr int H = 512;
constexpr int K = 24;
constexpr int G = 4 * H;          // 2048
constexpr int H2 = 2 * H;         // 1024
constexpr int START_TAG = 22;
constexpr int STOP_TAG = 23;
constexpr float NEG = -10000.0f;
constexpr int M_ROWS = B * T;     // 32768

constexpr int NBLK = 128;         // persistent recurrence blocks
constexpr int WKP = 36;           // ws row stride (floats)

// ------------------------- device scratch (static, no allocs) ----------------
__device__ float g_x[B * T * E];
__device__ float g_xg[2][T * G * B];          // [dir][(t*G+n)*B + b]
__device__ float g_h0[B * T * H2];
__device__ float g_h1[B * T * H2];
__device__ float g_hbuf[2][2][H * B];         // [dir][parity][k*64+b]
__device__ float g_feats[B * T * K];
__device__ unsigned g_barcnt;
__device__ unsigned g_bargen;

// ------------------------- small helpers -------------------------------------
static __device__ __forceinline__ unsigned smem_u32(const void* p) {
    unsigned r;
    asm("{ .reg .u64 t; cvta.to.shared.u64 t, %1; cvt.u32.u64 %0, t; }"
        : "=r"(r) : "l"(p));
    return r;
}
static __device__ __forceinline__ void cp_async16(unsigned dst, const void* src) {
    asm volatile("cp.async.cg.shared.global [%0], [%1], 16;\n" :: "r"(dst), "l"(src));
}
static __device__ __forceinline__ void cp_commit() {
    asm volatile("cp.async.commit_group;\n" ::: "memory");
}
template <int N>
static __device__ __forceinline__ void cp_wait() {
    asm volatile("cp.async.wait_group %0;\n" :: "n"(N) : "memory");
}

// packed f32x2 helpers (sm_100a)
static __device__ __forceinline__ unsigned long long pack2(float x, float y) {
    unsigned long long r;
    asm("mov.b64 %0, {%1, %2};" : "=l"(r) : "f"(x), "f"(y));
    return r;
}
static __device__ __forceinline__ void fma2(unsigned long long& d,
                                            unsigned long long a,
                                            unsigned long long b) {
    asm("fma.rn.f32x2 %0, %1, %2, %3;" : "=l"(d) : "l"(a), "l"(b), "l"(d));
}
static __device__ __forceinline__ float2 unpack2(unsigned long long v) {
    float2 f;
    asm("mov.b64 {%0, %1}, %2;" : "=f"(f.x), "=f"(f.y) : "l"(v));
    return f;
}

// ------------------------- embedding lookup ----------------------------------
__global__ void embed_kernel(const int* __restrict__ sentence,
                             const float* __restrict__ embed) {
    int i = blockIdx.x * blockDim.x + threadIdx.x;
    if (i >= B * T * E) return;
    int e = i % E;
    int bt = i / E;
    g_x[i] = embed[(long long)sentence[bt] * E + e];
}

// ------------------------- big GEMM: xg_t = A * W^T + bias -------------------
// 128x128 tile, BK=16, 256 threads, 8x8 microtile, f32x2 packed FMA.
__global__ __launch_bounds__(256)
void gemm_bias_kernel(int a_sel, const float* __restrict__ W,
                      const float* __restrict__ bias, int c_dir, int Kd) {
    const float* __restrict__ A = a_sel ? g_h0 : g_x;
    float* __restrict__ C = g_xg[c_dir];

    __shared__ float As[2][16][132];
    __shared__ float Ws[2][16][132];

    int n0 = blockIdx.x * 128;
    int m0 = blockIdx.y * 128;
    int tid = threadIdx.x;
    int tx = tid & 15;
    int ty = tid >> 4;
    int tm0 = ty * 8;
    int tn0 = tx * 8;

    int lrow0 = (tid * 2) >> 2;
    int lkc0 = (tid * 2) & 3;
    int lrow1 = (tid * 2 + 1) >> 2;
    int lkc1 = (tid * 2 + 1) & 3;

    unsigned long long acc2[8][4] = {};   // (n-pair) packed accumulators
    float4 ra0, ra1, rw0, rw1;

    ra0 = *(const float4*)&A[(size_t)(m0 + lrow0) * Kd + lkc0 * 4];
    ra1 = *(const float4*)&A[(size_t)(m0 + lrow1) * Kd + lkc1 * 4];
    rw0 = *(const float4*)&W[(size_t)(n0 + lrow0) * Kd + lkc0 * 4];
    rw1 = *(const float4*)&W[(size_t)(n0 + lrow1) * Kd + lkc1 * 4];
    {
        float* a0 = &As[0][lkc0 * 4][lrow0];
        a0[0 * 132] = ra0.x; a0[1 * 132] = ra0.y; a0[2 * 132] = ra0.z; a0[3 * 132] = ra0.w;
        float* a1 = &As[0][lkc1 * 4][lrow1];
        a1[0 * 132] = ra1.x; a1[1 * 132] = ra1.y; a1[2 * 132] = ra1.z; a1[3 * 132] = ra1.w;
        float* w0 = &Ws[0][lkc0 * 4][lrow0];
        w0[0 * 132] = rw0.x; w0[1 * 132] = rw0.y; w0[2 * 132] = rw0.z; w0[3 * 132] = rw0.w;
        float* w1 = &Ws[0][lkc1 * 4][lrow1];
        w1[0 * 132] = rw1.x; w1[1 * 132] = rw1.y; w1[2 * 132] = rw1.z; w1[3 * 132] = rw1.w;
    }
    __syncthreads();

    int nK = Kd / 16;
    for (int kt = 0; kt < nK; kt++) {
        int buf = kt & 1;
        if (kt + 1 < nK) {
            int k0 = (kt + 1) * 16;
            ra0 = *(const float4*)&A[(size_t)(m0 + lrow0) * Kd + k0 + lkc0 * 4];
            ra1 = *(const float4*)&A[(size_t)(m0 + lrow1) * Kd + k0 + lkc1 * 4];
            rw0 = *(const float4*)&W[(size_t)(n0 + lrow0) * Kd + k0 + lkc0 * 4];
            rw1 = *(const float4*)&W[(size_t)(n0 + lrow1) * Kd + k0 + lkc1 * 4];
        }
        #pragma unroll
        for (int k = 0; k < 16; k++) {
            float4 a0 = *(const float4*)&As[buf][k][tm0];
            float4 a1 = *(const float4*)&As[buf][k][tm0 + 4];
            ulonglong2 wA = *(const ulonglong2*)&Ws[buf][k][tn0];
            ulonglong2 wB = *(const ulonglong2*)&Ws[buf][k][tn0 + 4];
            unsigned long long wp[4] = {wA.x, wA.y, wB.x, wB.y};
            float av[8] = {a0.x, a0.y, a0.z, a0.w, a1.x, a1.y, a1.z, a1.w};
            #pragma unroll
            for (int i = 0; i < 8; i++) {
                unsigned long long ad = pack2(av[i], av[i]);
                #pragma unroll
                for (int j = 0; j < 4; j++)
                    fma2(acc2[i][j], ad, wp[j]);
            }
        }
        if (kt + 1 < nK) {
            int nbuf = buf ^ 1;
            float* a0 = &As[nbuf][lkc0 * 4][lrow0];
            a0[0 * 132] = ra0.x; a0[1 * 132] = ra0.y; a0[2 * 132] = ra0.z; a0[3 * 132] = ra0.w;
            float* a1 = &As[nbuf][lkc1 * 4][lrow1];
            a1[0 * 132] = ra1.x; a1[1 * 132] = ra1.y; a1[2 * 132] = ra1.z; a1[3 * 132] = ra1.w;
            float* w0 = &Ws[nbuf][lkc0 * 4][lrow0];
            w0[0 * 132] = rw0.x; w0[1 * 132] = rw0.y; w0[2 * 132] = rw0.z; w0[3 * 132] = rw0.w;
            float* w1 = &Ws[nbuf][lkc1 * 4][lrow1];
            w1[0 * 132] = rw1.x; w1[1 * 132] = rw1.y; w1[2 * 132] = rw1.z; w1[3 * 132] = rw1.w;
        }
        __syncthreads();
    }

    // epilogue: m = b*T + t ; single b per tile (T=512, tiles of 128)
    int b = m0 >> 9;
    int t0 = m0 & 511;
    #pragma unroll
    for (int i = 0; i < 8; i++) {
        int t = t0 + tm0 + i;
        #pragma unroll
        for (int j = 0; j < 4; j++) {
            float2 c = unpack2(acc2[i][j]);
            int n = n0 + tn0 + 2 * j;
            C[((size_t)t * G + n) * B + b] = c.x + bias[n];
            C[((size_t)t * G + n + 1) * B + b] = c.y + bias[n + 1];
        }
    }
}

// ------------------------- grid barrier --------------------------------------
__device__ __forceinline__ void grid_barrier() {
    __syncthreads();
    if (threadIdx.x == 0) {
        __threadfence();
        volatile unsigned* gv = &g_bargen;
        unsigned gen = *gv;
        unsigned ticket = atomicAdd(&g_barcnt, 1);
        if ((ticket + 1u) % (unsigned)NBLK == 0u) {
            atomicAdd(&g_bargen, 1u);
        } else {
            while (*gv == gen) { }
        }
        __threadfence();
    }
    __syncthreads();
}

// ------------------------- persistent bidirectional LSTM layer ---------------
__global__ __launch_bounds__(256, 1)
void lstm_layer_kernel(const float* __restrict__ whh_f,
                       const float* __restrict__ whh_b, int layer) {
    extern __shared__ float sm[];
    float* ws  = sm;                        // [512][WKP]
    float* hs  = ws + 512 * WKP;            // [2][128*64]
    float* gsm = hs + 2 * 128 * 64;         // [32][66]
    float* csm = gsm + 32 * 66;             // [8][64]

    int tid = threadIdx.x;
    int bx = blockIdx.x;
    int dir = bx >> 6;
    int h0 = (bx & 63) * 8;
    const float* __restrict__ Wm = dir ? whh_b : whh_f;
    const float* __restrict__ xg = g_xg[dir];
    float* __restrict__ hout = layer ? g_h1 : g_h0;

    int tx = tid & 31;          // b0 = tx*2
    int ty = tid >> 5;          // r0 = ty*4
    int b0 = tx * 2;
    int r0 = ty * 4;

    unsigned hs_u32 = smem_u32(hs);

    // ---- load + transpose weights into SMEM (once) ----
    {
        int r = tid >> 3;                   // 0..31
        int n = (r >> 3) * H + h0 + (r & 7);
        const float* wrow = &Wm[(size_t)n * H];
        #pragma unroll
        for (int it = 0; it < 16; it++) {
            int kc4 = (tid & 7) + it * 8;
            float4 w = *(const float4*)&wrow[kc4 * 4];
            float* d = &ws[(kc4 * 4) * WKP + r];
            d[0 * WKP] = w.x; d[1 * WKP] = w.y; d[2 * WKP] = w.z; d[3 * WKP] = w.w;
        }
    }

    for (int i = tid; i < 8 * 64; i += 256) csm[i] = 0.0f;
    {
        float* z = g_hbuf[dir][0];
        for (int i = tid; i < 8 * 64; i += 256) z[h0 * 64 + i] = 0.0f;
    }
    grid_barrier();

    for (int s = 0; s < T; s++) {
        int p = s & 1;
        int t = dir ? (T - 1 - s) : s;
        const float* __restrict__ hcur = g_hbuf[dir][p];
        float* __restrict__ hnext = g_hbuf[dir][p ^ 1];

        // prefetch xg (coalesced [t][n][b] layout); xv[i] = row r0+i, b pair
        float2 xv[4];
        #pragma unroll
        for (int i = 0; i < 4; i++) {
            int r = r0 + i;
            int n = (r >> 3) * H + h0 + (r & 7);
            xv[i] = __ldg((const float2*)&xg[((size_t)t * G + n) * B + b0]);
        }

        // acc2[pi][bj]: rows (r0+2pi, r0+2pi+1) packed, batch b0+bj
        unsigned long long acc2[2][2] = {};

        #pragma unroll
        for (int j = 0; j < 8; j++) {
            int f4 = tid + j * 256;
            cp_async16(hs_u32 + f4 * 16, &hcur[f4 * 4]);
        }
        cp_commit();

        #pragma unroll
        for (int c = 0; c < 4; c++) {
            int buf = c & 1;
            if (c < 3) {
                int nbuf = buf ^ 1;
                #pragma unroll
                for (int j = 0; j < 8; j++) {
                    int f4 = tid + j * 256;
                    cp_async16(hs_u32 + (nbuf * 8192 + f4 * 4) * 4,
                               &hcur[(c + 1) * 8192 + f4 * 4]);
                }
                cp_commit();
                cp_wait<1>();
            } else {
                cp_wait<0>();
            }
            __syncthreads();

            const float* hb = &hs[buf * 8192];
            const float* wb = &ws[(c * 128) * WKP];
            #pragma unroll 4
            for (int k = 0; k < 128; k++) {
                ulonglong2 w2 = *(const ulonglong2*)&wb[k * WKP + r0];
                float2 h = *(const float2*)&hb[k * 64 + b0];
                unsigned long long hx = pack2(h.x, h.x);
                unsigned long long hy = pack2(h.y, h.y);
                fma2(acc2[0][0], w2.x, hx);
                fma2(acc2[0][1], w2.x, hy);
                fma2(acc2[1][0], w2.y, hx);
                fma2(acc2[1][1], w2.y, hy);
            }
            __syncthreads();
        }

        // unpack gates + add xg -> smem
        #pragma unroll
        for (int pi = 0; pi < 2; pi++) {
            float2 gb0 = unpack2(acc2[pi][0]);   // rows (r0+2pi, r0+2pi+1) @ b0
            float2 gb1 = unpack2(acc2[pi][1]);   // same rows @ b0+1
            int r = r0 + 2 * pi;
            gsm[r * 66 + b0]           = gb0.x + xv[2 * pi].x;
            gsm[r * 66 + b0 + 1]       = gb1.x + xv[2 * pi].y;
            gsm[(r + 1) * 66 + b0]     = gb0.y + xv[2 * pi + 1].x;
            gsm[(r + 1) * 66 + b0 + 1] = gb1.y + xv[2 * pi + 1].y;
        }
        __syncthreads();

        // pointwise LSTM update
        #pragma unroll
        for (int rep = 0; rep < 2; rep++) {
            int e = tid + rep * 256;
            int hi = e >> 6;
            int b = e & 63;
            float gi = gsm[(0 * 8 + hi) * 66 + b];
            float gf = gsm[(1 * 8 + hi) * 66 + b];
            float gc = gsm[(2 * 8 + hi) * 66 + b];
            float go = gsm[(3 * 8 + hi) * 66 + b];

            float si = 1.0f / (1.0f + expf(-gi));
            float sf = 1.0f / (1.0f + expf(-gf));
            float so = 1.0f / (1.0f + expf(-go));

            float c = csm[hi * 64 + b];
            c = sf * c + si * tanhf(gc);
            float hn = so * tanhf(c);
            csm[hi * 64 + b] = c;

            hnext[(h0 + hi) * 64 + b] = hn;
            hout[((size_t)b * T + t) * H2 + dir * H + h0 + hi] = hn;
        }

        grid_barrier();
    }
}

// ------------------------- output projection (K=24) --------------------------
__global__ __launch_bounds__(256)
void proj_kernel(const float* __restrict__ w_out, const float* __restrict__ b_out) {
    int bt = blockIdx.x;
    int wid = threadIdx.x >> 5;
    int lane = threadIdx.x & 31;
    const float* hrow = g_h1 + (long long)bt * H2;

    for (int j = wid; j < K; j += 8) {
        const float* wr = w_out + j * H2;
        float s = 0.0f;
        for (int k = lane; k < H2; k += 32)
            s += hrow[k] * wr[k];
        #pragma unroll
        for (int off = 16; off; off >>= 1)
            s += __shfl_xor_sync(0xffffffff, s, off);
        if (lane == 0)
            g_feats[bt * K + j] = s + b_out[j];
    }
}

// ------------------------- Viterbi decode ------------------------------------
__global__ void viterbi_kernel(const float* __restrict__ trans,
                               float* __restrict__ out, int out_size) {
    int b = blockIdx.x;
    int tid = threadIdx.x;

    __shared__ float tr[K][K];
    __shared__ float v[K];
    __shared__ float vn[K];
    __shared__ unsigned char bp[T][K];

    for (int i = tid; i < K * K; i += 32)
        tr[i / K][i % K] = trans[i];
    if (tid < K)
        v[tid] = (tid == START_TAG) ? 0.0f : NEG;
    __syncthreads();

    for (int t = 0; t < T; t++) {
        if (tid < K) {
            float best = -3.4e38f;
            int arg = 0;
            #pragma unroll
            for (int kp = 0; kp < K; kp++) {
                float sc = v[kp] + tr[tid][kp];
                if (sc > best) { best = sc; arg = kp; }
            }
            vn[tid] = best + g_feats[(b * T + t) * K + tid];
            bp[t][tid] = (unsigned char)arg;
        }
        __syncthreads();
        if (tid < K) v[tid] = vn[tid];
        __syncthreads();
    }

    if (tid == 0) {
        float best = -3.4e38f;
        int arg = 0;
        for (int k = 0; k < K; k++) {
            float sc = v[k] + tr[STOP_TAG][k];
            if (sc > best) { best = sc; arg = k; }
        }
        if (out_size >= B + B * T) {
            out[b] = best;
            int tag = arg;
            for (int t = T - 1; t >= 0; t--) {
                out[B + b * T + t] = (float)tag;
                tag = bp[t][tag];
            }
        } else if (out_size >= B * T) {
            int tag = arg;
            for (int t = T - 1; t >= 0; t--) {
                out[b * T + t] = (float)tag;
                tag = bp[t][tag];
            }
        } else {
            out[b] = best;
        }
    }
}

// ------------------------- launch --------------------------------------------
extern "C" void kernel_launch(void* const* d_in, const int* in_sizes, int n_in,
                              void* d_out, int out_size) {
    const int*   sentence = (const int*)d_in[0];
    const float* embed    = (const float*)d_in[1];
    const float* w_ih_l0f = (const float*)d_in[2];
    const float* w_hh_l0f = (const float*)d_in[3];
    const float* b_l0f    = (const float*)d_in[4];
    const float* w_ih_l0b = (const float*)d_in[5];
    const float* w_hh_l0b = (const float*)d_in[6];
    const float* b_l0b    = (const float*)d_in[7];
    const float* w_ih_l1f = (const float*)d_in[8];
    const float* w_hh_l1f = (const float*)d_in[9];
    const float* b_l1f    = (const float*)d_in[10];
    const float* w_ih_l1b = (const float*)d_in[11];
    const float* w_hh_l1b = (const float*)d_in[12];
    const float* b_l1b    = (const float*)d_in[13];
    const float* w_out    = (const float*)d_in[14];
    const float* b_out    = (const float*)d_in[15];
    const float* trans    = (const float*)d_in[16];
    float* out = (float*)d_out;

    static bool attr_done = false;
    const int dyn_smem = (512 * WKP + 2 * 128 * 64 + 32 * 66 + 8 * 64) * 4;
    if (!attr_done) {
        cudaFuncSetAttribute(lstm_layer_kernel,
                             cudaFuncAttributeMaxDynamicSharedMemorySize, dyn_smem);
        attr_done = true;
    }

    embed_kernel<<<(B * T * E + 255) / 256, 256>>>(sentence, embed);

    dim3 ggrid(G / 128, M_ROWS / 128);
    gemm_bias_kernel<<<ggrid, 256>>>(0, w_ih_l0f, b_l0f, 0, E);
    gemm_bias_kernel<<<ggrid, 256>>>(0, w_ih_l0b, b_l0b, 1, E);

    lstm_layer_kernel<<<NBLK, 256, dyn_smem>>>(w_hh_l0f, w_hh_l0b, 0);

    gemm_bias_kernel<<<ggrid, 256>>>(1, w_ih_l1f, b_l1f, 0, H2);
    gemm_bias_kernel<<<ggrid, 256>>>(1, w_ih_l1b, b_l1b, 1, H2);

    lstm_layer_kernel<<<NBLK, 256, dyn_smem>>>(w_hh_l1f, w_hh_l1b, 1);

    proj_kernel<<<B * T, 256>>>(w_out, b_out);

    viterbi_kernel<<<B, 32>>>(trans, out, out_size);
}

// round 13
// speedup vs baseline: 1.3099x; 1.0416x over previous
#include <cuda_runtime.h>
#include <math.h>

// Problem constants
constexpr int B = 64;
constexpr int T = 512;
constexpr int E = 256;
constexpr int H = 512;
constexpr int K = 24;
constexpr int G = 4 * H;          // 2048
constexpr int H2 = 2 * H;         // 1024
constexpr int START_TAG = 22;
constexpr int STOP_TAG = 23;
constexpr float NEG = -10000.0f;
constexpr int M_ROWS = B * T;     // 32768

constexpr int NBLK = 128;         // persistent recurrence blocks (64 per dir)
constexpr int WKP = 36;           // ws row stride (floats)

// ------------------------- device scratch (static, no allocs) ----------------
__device__ float g_x[B * T * E];
__device__ float g_xg[2][T * G * B];          // [dir][(t*G+n)*B + b]
__device__ float g_h0[B * T * H2];
__device__ float g_h1[B * T * H2];
__device__ float g_hbuf[2][2][H * B];         // [dir][parity][k*64+b]
__device__ float g_feats[B * T * K];
__device__ unsigned g_barcnt2[2];
__device__ unsigned g_bargen2[2];

// ------------------------- small helpers -------------------------------------
static __device__ __forceinline__ unsigned smem_u32(const void* p) {
    unsigned r;
    asm("{ .reg .u64 t; cvta.to.shared.u64 t, %1; cvt.u32.u64 %0, t; }"
        : "=r"(r) : "l"(p));
    return r;
}
static __device__ __forceinline__ void cp_async16(unsigned dst, const void* src) {
    asm volatile("cp.async.cg.shared.global [%0], [%1], 16;\n" :: "r"(dst), "l"(src));
}
static __device__ __forceinline__ void cp_commit() {
    asm volatile("cp.async.commit_group;\n" ::: "memory");
}
template <int N>
static __device__ __forceinline__ void cp_wait() {
    asm volatile("cp.async.wait_group %0;\n" :: "n"(N) : "memory");
}

// packed f32x2 helpers
static __device__ __forceinline__ unsigned long long pack2(float x, float y) {
    unsigned long long r;
    asm("mov.b64 %0, {%1, %2};" : "=l"(r) : "f"(x), "f"(y));
    return r;
}
static __device__ __forceinline__ void fma2(unsigned long long& d,
                                            unsigned long long a,
                                            unsigned long long b) {
    asm("fma.rn.f32x2 %0, %1, %2, %3;" : "=l"(d) : "l"(a), "l"(b), "l"(d));
}
static __device__ __forceinline__ float2 unpack2(unsigned long long v) {
    float2 f;
    asm("mov.b64 {%0, %1}, %2;" : "=f"(f.x), "=f"(f.y) : "l"(v));
    return f;
}

// ------------------------- embedding lookup ----------------------------------
__global__ void embed_kernel(const int* __restrict__ sentence,
                             const float* __restrict__ embed) {
    int i = blockIdx.x * blockDim.x + threadIdx.x;
    if (i >= B * T * E) return;
    int e = i % E;
    int bt = i / E;
    g_x[i] = embed[(long long)sentence[bt] * E + e];
}

// ------------------------- big GEMM: xg_t = A * W^T + bias (R4 verbatim) -----
__global__ __launch_bounds__(256)
void gemm_bias_kernel(int a_sel, const float* __restrict__ W,
                      const float* __restrict__ bias, int c_dir, int Kd) {
    const float* __restrict__ A = a_sel ? g_h0 : g_x;
    float* __restrict__ C = g_xg[c_dir];

    __shared__ float As[2][16][132];
    __shared__ float Ws[2][16][132];

    int n0 = blockIdx.x * 128;
    int m0 = blockIdx.y * 128;
    int tid = threadIdx.x;
    int tx = tid & 15;
    int ty = tid >> 4;
    int tm0 = ty * 8;
    int tn0 = tx * 8;

    int lrow0 = (tid * 2) >> 2;
    int lkc0 = (tid * 2) & 3;
    int lrow1 = (tid * 2 + 1) >> 2;
    int lkc1 = (tid * 2 + 1) & 3;

    unsigned long long acc2[8][4] = {};
    float4 ra0, ra1, rw0, rw1;

    ra0 = *(const float4*)&A[(size_t)(m0 + lrow0) * Kd + lkc0 * 4];
    ra1 = *(const float4*)&A[(size_t)(m0 + lrow1) * Kd + lkc1 * 4];
    rw0 = *(const float4*)&W[(size_t)(n0 + lrow0) * Kd + lkc0 * 4];
    rw1 = *(const float4*)&W[(size_t)(n0 + lrow1) * Kd + lkc1 * 4];
    {
        float* a0 = &As[0][lkc0 * 4][lrow0];
        a0[0 * 132] = ra0.x; a0[1 * 132] = ra0.y; a0[2 * 132] = ra0.z; a0[3 * 132] = ra0.w;
        float* a1 = &As[0][lkc1 * 4][lrow1];
        a1[0 * 132] = ra1.x; a1[1 * 132] = ra1.y; a1[2 * 132] = ra1.z; a1[3 * 132] = ra1.w;
        float* w0 = &Ws[0][lkc0 * 4][lrow0];
        w0[0 * 132] = rw0.x; w0[1 * 132] = rw0.y; w0[2 * 132] = rw0.z; w0[3 * 132] = rw0.w;
        float* w1 = &Ws[0][lkc1 * 4][lrow1];
        w1[0 * 132] = rw1.x; w1[1 * 132] = rw1.y; w1[2 * 132] = rw1.z; w1[3 * 132] = rw1.w;
    }
    __syncthreads();

    int nK = Kd / 16;
    for (int kt = 0; kt < nK; kt++) {
        int buf = kt & 1;
        if (kt + 1 < nK) {
            int k0 = (kt + 1) * 16;
            ra0 = *(const float4*)&A[(size_t)(m0 + lrow0) * Kd + k0 + lkc0 * 4];
            ra1 = *(const float4*)&A[(size_t)(m0 + lrow1) * Kd + k0 + lkc1 * 4];
            rw0 = *(const float4*)&W[(size_t)(n0 + lrow0) * Kd + k0 + lkc0 * 4];
            rw1 = *(const float4*)&W[(size_t)(n0 + lrow1) * Kd + k0 + lkc1 * 4];
        }
        #pragma unroll
        for (int k = 0; k < 16; k++) {
            float4 a0 = *(const float4*)&As[buf][k][tm0];
            float4 a1 = *(const float4*)&As[buf][k][tm0 + 4];
            ulonglong2 wA = *(const ulonglong2*)&Ws[buf][k][tn0];
            ulonglong2 wB = *(const ulonglong2*)&Ws[buf][k][tn0 + 4];
            unsigned long long wp[4] = {wA.x, wA.y, wB.x, wB.y};
            float av[8] = {a0.x, a0.y, a0.z, a0.w, a1.x, a1.y, a1.z, a1.w};
            #pragma unroll
            for (int i = 0; i < 8; i++) {
                unsigned long long ad = pack2(av[i], av[i]);
                #pragma unroll
                for (int j = 0; j < 4; j++)
                    fma2(acc2[i][j], ad, wp[j]);
            }
        }
        if (kt + 1 < nK) {
            int nbuf = buf ^ 1;
            float* a0 = &As[nbuf][lkc0 * 4][lrow0];
            a0[0 * 132] = ra0.x; a0[1 * 132] = ra0.y; a0[2 * 132] = ra0.z; a0[3 * 132] = ra0.w;
            float* a1 = &As[nbuf][lkc1 * 4][lrow1];
            a1[0 * 132] = ra1.x; a1[1 * 132] = ra1.y; a1[2 * 132] = ra1.z; a1[3 * 132] = ra1.w;
            float* w0 = &Ws[nbuf][lkc0 * 4][lrow0];
            w0[0 * 132] = rw0.x; w0[1 * 132] = rw0.y; w0[2 * 132] = rw0.z; w0[3 * 132] = rw0.w;
            float* w1 = &Ws[nbuf][lkc1 * 4][lrow1];
            w1[0 * 132] = rw1.x; w1[1 * 132] = rw1.y; w1[2 * 132] = rw1.z; w1[3 * 132] = rw1.w;
        }
        __syncthreads();
    }

    int b = m0 >> 9;
    int t0 = m0 & 511;
    #pragma unroll
    for (int i = 0; i < 8; i++) {
        int t = t0 + tm0 + i;
        #pragma unroll
        for (int j = 0; j < 4; j++) {
            float2 c = unpack2(acc2[i][j]);
            int n = n0 + tn0 + 2 * j;
            C[((size_t)t * G + n) * B + b] = c.x + bias[n];
            C[((size_t)t * G + n + 1) * B + b] = c.y + bias[n + 1];
        }
    }
}

// ------------------------- per-direction grid barrier -------------------------
__device__ __forceinline__ void grid_barrier_dir(int dir) {
    __syncthreads();
    if (threadIdx.x == 0) {
        __threadfence();
        volatile unsigned* gv = &g_bargen2[dir];
        unsigned gen = *gv;
        unsigned ticket = atomicAdd(&g_barcnt2[dir], 1);
        if ((ticket + 1u) % 64u == 0u) {
            atomicAdd(&g_bargen2[dir], 1u);
        } else {
            while (*gv == gen) { }
        }
        __threadfence();
    }
    __syncthreads();
}

// ------------------------- persistent bidirectional LSTM layer ---------------
// Block bx: dir = bx>>6, h-slice h0 = (bx&63)*8.
// ws permuted: ws[k][hidx*4 + gate] so each thread (ty=hidx, lane: b pair)
// owns all 4 gates of one h-index -> pointwise fully in registers.
// 2 cp.async-double-buffered chunks of 256 k per step; c-state in registers.
__global__ __launch_bounds__(256, 1)
void lstm_layer_kernel(const float* __restrict__ whh_f,
                       const float* __restrict__ whh_b, int layer) {
    extern __shared__ float sm[];
    float* ws = sm;                         // [512][WKP]
    float* hs = ws + 512 * WKP;             // [2][256*64]

    int tid = threadIdx.x;
    int bx = blockIdx.x;
    int dir = bx >> 6;
    int h0 = (bx & 63) * 8;
    const float* __restrict__ Wm = dir ? whh_b : whh_f;
    const float* __restrict__ xg = g_xg[dir];
    float* __restrict__ hout = layer ? g_h1 : g_h0;

    int lane = tid & 31;        // b0 = lane*2
    int ty = tid >> 5;          // hidx = ty (0..7)
    int b0 = lane * 2;
    int q0 = ty * 4;            // ws column base: 4 gates of hidx=ty

    unsigned hs_u32 = smem_u32(hs);

    // ---- load + transpose weights into SMEM, gate-permuted (once) ----
    {
        int r = tid >> 3;                   // 0..31  (gate*8 + hidx)
        int gate = r >> 3;
        int hidx = r & 7;
        int q = hidx * 4 + gate;
        int n = gate * H + h0 + hidx;
        const float* wrow = &Wm[(size_t)n * H];
        #pragma unroll
        for (int it = 0; it < 16; it++) {
            int kc4 = (tid & 7) + it * 8;   // float4 idx 0..127
            float4 w = *(const float4*)&wrow[kc4 * 4];
            float* d = &ws[(kc4 * 4) * WKP + q];
            d[0 * WKP] = w.x; d[1 * WKP] = w.y; d[2 * WKP] = w.z; d[3 * WKP] = w.w;
        }
    }

    // zero parity-0 h slice
    {
        float* z = g_hbuf[dir][0];
        for (int i = tid; i < 8 * 64; i += 256) z[h0 * 64 + i] = 0.0f;
    }
    float c_reg0 = 0.0f, c_reg1 = 0.0f;     // c for (hidx=ty, b0), (ty, b0+1)
    grid_barrier_dir(dir);

    for (int s = 0; s < T; s++) {
        int p = s & 1;
        int t = dir ? (T - 1 - s) : s;
        const float* __restrict__ hcur = g_hbuf[dir][p];
        float* __restrict__ hnext = g_hbuf[dir][p ^ 1];

        // xg prefetch: 4 gates x (b0, b0+1)
        float2 xv[4];
        #pragma unroll
        for (int g = 0; g < 4; g++)
            xv[g] = __ldg((const float2*)&xg[((size_t)t * G + g * H + h0 + ty) * B + b0]);

        // chunk 0 (k 0..255) into buf0, chunk 1 into buf1 (pipelined)
        #pragma unroll
        for (int j = 0; j < 16; j++) {
            int f4 = tid + j * 256;         // 0..4095 float4s
            cp_async16(hs_u32 + f4 * 16, &hcur[f4 * 4]);
        }
        cp_commit();
        #pragma unroll
        for (int j = 0; j < 16; j++) {
            int f4 = tid + j * 256;
            cp_async16(hs_u32 + (16384 + f4 * 4) * 4, &hcur[16384 + f4 * 4]);
        }
        cp_commit();

        unsigned long long acc2[2][2] = {}; // [gate-pair][b]

        #pragma unroll
        for (int c = 0; c < 2; c++) {
            if (c == 0) { cp_wait<1>(); } else { cp_wait<0>(); }
            __syncthreads();

            const float* hb = &hs[c * 16384];
            const float* wb = &ws[(c * 256) * WKP];
            #pragma unroll 4
            for (int k = 0; k < 256; k++) {
                ulonglong2 w2 = *(const ulonglong2*)&wb[k * WKP + q0];
                float2 h = *(const float2*)&hb[k * 64 + b0];
                unsigned long long hx = pack2(h.x, h.x);
                unsigned long long hy = pack2(h.y, h.y);
                fma2(acc2[0][0], w2.x, hx);   // gates (i,f) @ b0
                fma2(acc2[0][1], w2.x, hy);   // gates (i,f) @ b0+1
                fma2(acc2[1][0], w2.y, hx);   // gates (g,o) @ b0
                fma2(acc2[1][1], w2.y, hy);   // gates (g,o) @ b0+1
            }
        }

        // pointwise LSTM in registers
        float2 u00 = unpack2(acc2[0][0]);   // (i, f) @ b0
        float2 u10 = unpack2(acc2[1][0]);   // (g, o) @ b0
        float2 u01 = unpack2(acc2[0][1]);   // (i, f) @ b0+1
        float2 u11 = unpack2(acc2[1][1]);   // (g, o) @ b0+1

        float gi0 = u00.x + xv[0].x, gf0 = u00.y + xv[1].x;
        float gc0 = u10.x + xv[2].x, go0 = u10.y + xv[3].x;
        float gi1 = u01.x + xv[0].y, gf1 = u01.y + xv[1].y;
        float gc1 = u11.x + xv[2].y, go1 = u11.y + xv[3].y;

        float si0 = 1.0f / (1.0f + expf(-gi0));
        float sf0 = 1.0f / (1.0f + expf(-gf0));
        float so0 = 1.0f / (1.0f + expf(-go0));
        float si1 = 1.0f / (1.0f + expf(-gi1));
        float sf1 = 1.0f / (1.0f + expf(-gf1));
        float so1 = 1.0f / (1.0f + expf(-go1));

        c_reg0 = sf0 * c_reg0 + si0 * tanhf(gc0);
        c_reg1 = sf1 * c_reg1 + si1 * tanhf(gc1);
        float hn0 = so0 * tanhf(c_reg0);
        float hn1 = so1 * tanhf(c_reg1);

        *(float2*)&hnext[(h0 + ty) * 64 + b0] = make_float2(hn0, hn1);
        size_t ob = ((size_t)b0 * T + t) * H2 + dir * H + h0 + ty;
        hout[ob] = hn0;
        hout[ob + (size_t)T * H2] = hn1;    // b0+1

        grid_barrier_dir(dir);
    }
}

// ------------------------- output projection (K=24) --------------------------
__global__ __launch_bounds__(256)
void proj_kernel(const float* __restrict__ w_out, const float* __restrict__ b_out) {
    int bt = blockIdx.x;
    int wid = threadIdx.x >> 5;
    int lane = threadIdx.x & 31;
    const float* hrow = g_h1 + (long long)bt * H2;

    for (int j = wid; j < K; j += 8) {
        const float* wr = w_out + j * H2;
        float s = 0.0f;
        for (int k = lane; k < H2; k += 32)
            s += hrow[k] * wr[k];
        #pragma unroll
        for (int off = 16; off; off >>= 1)
            s += __shfl_xor_sync(0xffffffff, s, off);
        if (lane == 0)
            g_feats[bt * K + j] = s + b_out[j];
    }
}

// ------------------------- Viterbi decode ------------------------------------
__global__ void viterbi_kernel(const float* __restrict__ trans,
                               float* __restrict__ out, int out_size) {
    int b = blockIdx.x;
    int tid = threadIdx.x;

    __shared__ float tr[K][K];
    __shared__ float v[K];
    __shared__ float vn[K];
    __shared__ unsigned char bp[T][K];

    for (int i = tid; i < K * K; i += 32)
        tr[i / K][i % K] = trans[i];
    if (tid < K)
        v[tid] = (tid == START_TAG) ? 0.0f : NEG;
    __syncthreads();

    for (int t = 0; t < T; t++) {
        if (tid < K) {
            float best = -3.4e38f;
            int arg = 0;
            #pragma unroll
            for (int kp = 0; kp < K; kp++) {
                float sc = v[kp] + tr[tid][kp];
                if (sc > best) { best = sc; arg = kp; }
            }
            vn[tid] = best + g_feats[(b * T + t) * K + tid];
            bp[t][tid] = (unsigned char)arg;
        }
        __syncthreads();
        if (tid < K) v[tid] = vn[tid];
        __syncthreads();
    }

    if (tid == 0) {
        float best = -3.4e38f;
        int arg = 0;
        for (int k = 0; k < K; k++) {
            float sc = v[k] + tr[STOP_TAG][k];
            if (sc > best) { best = sc; arg = k; }
        }
        if (out_size >= B + B * T) {
            out[b] = best;
            int tag = arg;
            for (int t = T - 1; t >= 0; t--) {
                out[B + b * T + t] = (float)tag;
                tag = bp[t][tag];
            }
        } else if (out_size >= B * T) {
            int tag = arg;
            for (int t = T - 1; t >= 0; t--) {
                out[b * T + t] = (float)tag;
                tag = bp[t][tag];
            }
        } else {
            out[b] = best;
        }
    }
}

// ------------------------- launch --------------------------------------------
extern "C" void kernel_launch(void* const* d_in, const int* in_sizes, int n_in,
                              void* d_out, int out_size) {
    const int*   sentence = (const int*)d_in[0];
    const float* embed    = (const float*)d_in[1];
    const float* w_ih_l0f = (const float*)d_in[2];
    const float* w_hh_l0f = (const float*)d_in[3];
    const float* b_l0f    = (const float*)d_in[4];
    const float* w_ih_l0b = (const float*)d_in[5];
    const float* w_hh_l0b = (const float*)d_in[6];
    const float* b_l0b    = (const float*)d_in[7];
    const float* w_ih_l1f = (const float*)d_in[8];
    const float* w_hh_l1f = (const float*)d_in[9];
    const float* b_l1f    = (const float*)d_in[10];
    const float* w_ih_l1b = (const float*)d_in[11];
    const float* w_hh_l1b = (const float*)d_in[12];
    const float* b_l1b    = (const float*)d_in[13];
    const float* w_out    = (const float*)d_in[14];
    const float* b_out    = (const float*)d_in[15];
    const float* trans    = (const float*)d_in[16];
    float* out = (float*)d_out;

    const int lstm_smem = (512 * WKP + 2 * 256 * 64) * 4;   // 204800 B
    cudaFuncSetAttribute(lstm_layer_kernel,
                         cudaFuncAttributeMaxDynamicSharedMemorySize, lstm_smem);

    // 1. embedding
    embed_kernel<<<(B * T * E + 255) / 256, 256>>>(sentence, embed);

    // 2. layer-0 input-gate GEMMs (Kd=256)
    dim3 ggrid(G / 128, M_ROWS / 128);
    gemm_bias_kernel<<<ggrid, 256>>>(0, w_ih_l0f, b_l0f, 0, E);
    gemm_bias_kernel<<<ggrid, 256>>>(0, w_ih_l0b, b_l0b, 1, E);

    // 3. layer-0 recurrence (persistent)
    lstm_layer_kernel<<<NBLK, 256, lstm_smem>>>(w_hh_l0f, w_hh_l0b, 0);

    // 4. layer-1 input-gate GEMMs (Kd=1024)
    gemm_bias_kernel<<<ggrid, 256>>>(1, w_ih_l1f, b_l1f, 0, H2);
    gemm_bias_kernel<<<ggrid, 256>>>(1, w_ih_l1b, b_l1b, 1, H2);

    // 5. layer-1 recurrence
    lstm_layer_kernel<<<NBLK, 256, lstm_smem>>>(w_hh_l1f, w_hh_l1b, 1);

    // 6. emission features
    proj_kernel<<<B * T, 256>>>(w_out, b_out);

    // 7. Viterbi decode + output
    viterbi_kernel<<<B, 32>>>(trans, out, out_size);
}